// round 1
// baseline (speedup 1.0000x reference)
#include <cuda_runtime.h>
#include <cstdint>
#include <cstddef>

#define B_    64
#define T_    512
#define H_    256
#define G4    1024
#define KIN   768
#define CLUSTER 8
#define NB    4      // batches per cluster
#define JS    32     // h-slice per CTA
#define RROWS 128    // gate rows per CTA (4 gates x 32)

// ---------------- scratch (static device globals; no cudaMalloc) ----------------
__device__ float g_gp[(size_t)B_ * T_ * G4];   // gates_pre [b][t][1024] (Hi part + bias), 128 MB
__device__ float g_sp[B_ * T_ * 2];            // score_pre [b][t][2]
__device__ float g_WihT[KIN * G4];             // Wih[:,32:800] transposed -> [k][n]
__device__ float g_bias[G4];                   // bih + bhh
__device__ float g_tagc[3 * G4];               // tag_em @ Wih[:,0:32]^T  (row 2 = zeros)

// ---------------- small PTX helpers ----------------
__device__ __forceinline__ uint32_t ctarank_() {
    uint32_t r; asm("mov.u32 %0, %%cluster_ctarank;" : "=r"(r)); return r;
}
__device__ __forceinline__ void cluster_sync_() {
    asm volatile("barrier.cluster.arrive.aligned;\n\tbarrier.cluster.wait.aligned;" ::: "memory");
}
__device__ __forceinline__ void st_cluster_f32(uint32_t saddr, uint32_t dst, float v) {
    asm volatile(
        "{\n\t.reg .b32 ra;\n\t"
        "mapa.shared::cluster.u32 ra, %0, %1;\n\t"
        "st.shared::cluster.f32 [ra], %2;\n\t}"
        :: "r"(saddr), "r"(dst), "f"(v) : "memory");
}

// ---------------- prep: transpose Wih slice, bias, tag contributions ----------------
__global__ void prep_kernel(const float* __restrict__ Wih,
                            const float* __restrict__ bih,
                            const float* __restrict__ bhh,
                            const float* __restrict__ tag_em) {
    int blk = blockIdx.x;
    int tid = threadIdx.x;
    if (blk < KIN) {
        int k = blk;
        for (int n = tid; n < G4; n += 256)
            g_WihT[k * G4 + n] = Wih[n * 800 + 32 + k];
    } else {
        for (int n = tid; n < G4; n += 256) {
            g_bias[n] = bih[n] + bhh[n];
            float t0 = 0.f, t1 = 0.f;
            #pragma unroll
            for (int e = 0; e < 32; ++e) {
                float w = Wih[n * 800 + e];
                t0 = fmaf(tag_em[e], w, t0);
                t1 = fmaf(tag_em[32 + e], w, t1);
            }
            g_tagc[n]            = t0;
            g_tagc[G4 + n]       = t1;
            g_tagc[2 * G4 + n]   = 0.f;
        }
    }
}

// ---------------- SGEMM: g_gp = sents @ WihT + bias  (M=32768, N=1024, K=768) ----------------
__global__ __launch_bounds__(256) void sgemm_kernel(const float* __restrict__ A) {
    __shared__ float As[2][16][128];   // stored transposed: [k][m]
    __shared__ float Bs[2][16][128];   // [k][n]

    const int tid = threadIdx.x;
    const int bn = blockIdx.x, bm = blockIdx.y;
    const int tx = tid & 15, ty = tid >> 4;

    const int arow = tid >> 2, ak4 = tid & 3;        // A: 2 float4 per thread
    const int brow = tid >> 5, bn4 = tid & 31;       // B: 2 float4 per thread

    const float* Ab = A + (size_t)(bm * 128) * KIN;
    const float* Bb = g_WihT + bn * 128;

    float acc[8][8];
    #pragma unroll
    for (int i = 0; i < 8; ++i)
        #pragma unroll
        for (int j = 0; j < 8; ++j) acc[i][j] = 0.f;

    // prologue: buffer 0
    {
        float4 a0 = *(const float4*)&Ab[(size_t)arow * KIN + ak4 * 4];
        float4 a1 = *(const float4*)&Ab[(size_t)(arow + 64) * KIN + ak4 * 4];
        float4 b0 = *(const float4*)&Bb[(size_t)brow * G4 + bn4 * 4];
        float4 b1 = *(const float4*)&Bb[(size_t)(brow + 8) * G4 + bn4 * 4];
        As[0][ak4 * 4 + 0][arow] = a0.x; As[0][ak4 * 4 + 1][arow] = a0.y;
        As[0][ak4 * 4 + 2][arow] = a0.z; As[0][ak4 * 4 + 3][arow] = a0.w;
        As[0][ak4 * 4 + 0][arow + 64] = a1.x; As[0][ak4 * 4 + 1][arow + 64] = a1.y;
        As[0][ak4 * 4 + 2][arow + 64] = a1.z; As[0][ak4 * 4 + 3][arow + 64] = a1.w;
        *(float4*)&Bs[0][brow][bn4 * 4]     = b0;
        *(float4*)&Bs[0][brow + 8][bn4 * 4] = b1;
    }
    __syncthreads();

    const int NKT = KIN / 16;  // 48
    for (int kt = 0; kt < NKT; ++kt) {
        const int cur = kt & 1;
        float4 na0, na1, nb0, nb1;
        if (kt + 1 < NKT) {
            const float* Ak = Ab + (kt + 1) * 16;
            na0 = *(const float4*)&Ak[(size_t)arow * KIN + ak4 * 4];
            na1 = *(const float4*)&Ak[(size_t)(arow + 64) * KIN + ak4 * 4];
            const float* Bk = Bb + (size_t)(kt + 1) * 16 * G4;
            nb0 = *(const float4*)&Bk[(size_t)brow * G4 + bn4 * 4];
            nb1 = *(const float4*)&Bk[(size_t)(brow + 8) * G4 + bn4 * 4];
        }
        #pragma unroll
        for (int k = 0; k < 16; ++k) {
            float4 av0 = *(const float4*)&As[cur][k][ty * 8];
            float4 av1 = *(const float4*)&As[cur][k][ty * 8 + 4];
            float4 bv0 = *(const float4*)&Bs[cur][k][tx * 8];
            float4 bv1 = *(const float4*)&Bs[cur][k][tx * 8 + 4];
            float am[8] = {av0.x, av0.y, av0.z, av0.w, av1.x, av1.y, av1.z, av1.w};
            float bv[8] = {bv0.x, bv0.y, bv0.z, bv0.w, bv1.x, bv1.y, bv1.z, bv1.w};
            #pragma unroll
            for (int i = 0; i < 8; ++i)
                #pragma unroll
                for (int j = 0; j < 8; ++j)
                    acc[i][j] = fmaf(am[i], bv[j], acc[i][j]);
        }
        if (kt + 1 < NKT) {
            const int nxt = cur ^ 1;
            As[nxt][ak4 * 4 + 0][arow] = na0.x; As[nxt][ak4 * 4 + 1][arow] = na0.y;
            As[nxt][ak4 * 4 + 2][arow] = na0.z; As[nxt][ak4 * 4 + 3][arow] = na0.w;
            As[nxt][ak4 * 4 + 0][arow + 64] = na1.x; As[nxt][ak4 * 4 + 1][arow + 64] = na1.y;
            As[nxt][ak4 * 4 + 2][arow + 64] = na1.z; As[nxt][ak4 * 4 + 3][arow + 64] = na1.w;
            *(float4*)&Bs[nxt][brow][bn4 * 4]     = nb0;
            *(float4*)&Bs[nxt][brow + 8][bn4 * 4] = nb1;
        }
        __syncthreads();
    }

    const int m0 = bm * 128 + ty * 8;
    const int n0 = bn * 128 + tx * 8;
    float4 bias0 = *(const float4*)&g_bias[n0];
    float4 bias1 = *(const float4*)&g_bias[n0 + 4];
    #pragma unroll
    for (int i = 0; i < 8; ++i) {
        float4 v0 = make_float4(acc[i][0] + bias0.x, acc[i][1] + bias0.y,
                                acc[i][2] + bias0.z, acc[i][3] + bias0.w);
        float4 v1 = make_float4(acc[i][4] + bias1.x, acc[i][5] + bias1.y,
                                acc[i][6] + bias1.z, acc[i][7] + bias1.w);
        *(float4*)&g_gp[(size_t)(m0 + i) * G4 + n0]     = v0;
        *(float4*)&g_gp[(size_t)(m0 + i) * G4 + n0 + 4] = v1;
    }
}

// ---------------- score_pre: g_sp[m][k] = sents[m] . Waff[k,256:1024] + baff[k] ----------------
__global__ __launch_bounds__(256) void spre_kernel(const float* __restrict__ sents,
                                                   const float* __restrict__ Waff,
                                                   const float* __restrict__ baff) {
    int warp = (blockIdx.x * 256 + threadIdx.x) >> 5;
    int lane = threadIdx.x & 31;
    if (warp >= B_ * T_) return;
    const float4* a  = (const float4*)(sents + (size_t)warp * KIN);
    const float4* w0 = (const float4*)(Waff + 256);
    const float4* w1 = (const float4*)(Waff + G4 + 256);
    float s0 = 0.f, s1 = 0.f;
    #pragma unroll
    for (int i = lane; i < KIN / 4; i += 32) {
        float4 av = a[i], v0 = w0[i], v1 = w1[i];
        s0 = fmaf(av.x, v0.x, s0); s0 = fmaf(av.y, v0.y, s0);
        s0 = fmaf(av.z, v0.z, s0); s0 = fmaf(av.w, v0.w, s0);
        s1 = fmaf(av.x, v1.x, s1); s1 = fmaf(av.y, v1.y, s1);
        s1 = fmaf(av.z, v1.z, s1); s1 = fmaf(av.w, v1.w, s1);
    }
    #pragma unroll
    for (int o = 16; o > 0; o >>= 1) {
        s0 += __shfl_xor_sync(0xffffffffu, s0, o);
        s1 += __shfl_xor_sync(0xffffffffu, s1, o);
    }
    if (lane == 0) {
        g_sp[(size_t)warp * 2]     = s0 + baff[0];
        g_sp[(size_t)warp * 2 + 1] = s1 + baff[1];
    }
}

// ---------------- recurrence: persistent, 16 clusters x 8 CTAs, Whh resident in SMEM ----------------
struct RnnSmem {
    float whh[RROWS][260];     // padded stride 260 -> conflict-free LDS.128
    float h[NB][H_];           // masked h_{t-1}, full
    float hnew[2][NB][H_];     // double-buffered exchange target (unmasked h_t)
    float c[NB][JS];           // masked c slice (own j range)
    float gates[NB][4][JS];
    float tagc[3][RROWS];
    float waffh[2][H_];
    float score[NB][2];
    int   pred[NB];
};

__device__ __forceinline__ float sigf(float x) { return 1.f / (1.f + expf(-x)); }

__global__ void __cluster_dims__(CLUSTER, 1, 1) __launch_bounds__(256, 1)
rnn_kernel(const float* __restrict__ mask,
           const float* __restrict__ Whh,
           const float* __restrict__ Waff,
           float* __restrict__ out) {
    extern __shared__ unsigned char smem_raw[];
    RnnSmem& s = *reinterpret_cast<RnnSmem*>(smem_raw);

    const int tid  = threadIdx.x;
    const uint32_t rank = ctarank_();
    const int cid   = blockIdx.x >> 3;
    const int bbase = cid * NB;

    // ---- init: load Whh slice, tag contribs, Waff_h; zero state ----
    for (int idx = tid; idx < RROWS * H_; idx += 256) {
        int rr = idx >> 8, k = idx & 255;
        int grow = ((rr >> 5) << 8) + (int)rank * JS + (rr & 31);
        s.whh[rr][k] = Whh[(size_t)grow * H_ + k];
    }
    for (int rr = tid; rr < RROWS; rr += 256) {
        int grow = ((rr >> 5) << 8) + (int)rank * JS + (rr & 31);
        s.tagc[0][rr] = g_tagc[grow];
        s.tagc[1][rr] = g_tagc[G4 + grow];
        s.tagc[2][rr] = 0.f;
    }
    for (int i = tid; i < 2 * H_; i += 256) s.waffh[i >> 8][i & 255] = Waff[(i >> 8) * G4 + (i & 255)];
    for (int i = tid; i < NB * H_; i += 256) s.h[i >> 8][i & 255] = 0.f;
    for (int i = tid; i < NB * JS; i += 256) s.c[i >> 5][i & 31] = 0.f;
    if (tid < NB) s.pred[tid] = 2;   // step 0: zero yem contribution
    __syncthreads();

    const int r  = tid & 127;
    const int bp = tid >> 7;
    const int b0 = bp * 2, b1 = b0 + 1;
    const int gg_ = r >> 5, jj_ = r & 31;
    const int grow = gg_ * 256 + (int)rank * JS + jj_;
    const size_t gpb0 = ((size_t)(bbase + b0) * T_) * G4 + grow;
    const size_t gpb1 = ((size_t)(bbase + b1) * T_) * G4 + grow;

    for (int t = 0; t < T_; ++t) {
        // prefetch this step's precomputed gate contributions (latency hidden by matvec)
        float gp0 = __ldg(&g_gp[gpb0 + (size_t)t * G4]);
        float gp1 = __ldg(&g_gp[gpb1 + (size_t)t * G4]);

        // ---- matvec: 2 outputs per thread (row r x batches b0,b1), K=256 ----
        const float4* w4 = reinterpret_cast<const float4*>(s.whh[r]);
        const float4* x0 = reinterpret_cast<const float4*>(s.h[b0]);
        const float4* x1 = reinterpret_cast<const float4*>(s.h[b1]);
        float a0e = 0.f, a0o = 0.f, a1e = 0.f, a1o = 0.f;
        #pragma unroll 8
        for (int kk = 0; kk < 64; kk += 2) {
            float4 w0 = w4[kk],   w1 = w4[kk + 1];
            float4 q0 = x0[kk],   q1 = x0[kk + 1];
            float4 p0 = x1[kk],   p1 = x1[kk + 1];
            a0e = fmaf(w0.x, q0.x, a0e); a0e = fmaf(w0.y, q0.y, a0e);
            a0e = fmaf(w0.z, q0.z, a0e); a0e = fmaf(w0.w, q0.w, a0e);
            a1e = fmaf(w0.x, p0.x, a1e); a1e = fmaf(w0.y, p0.y, a1e);
            a1e = fmaf(w0.z, p0.z, a1e); a1e = fmaf(w0.w, p0.w, a1e);
            a0o = fmaf(w1.x, q1.x, a0o); a0o = fmaf(w1.y, q1.y, a0o);
            a0o = fmaf(w1.z, q1.z, a0o); a0o = fmaf(w1.w, q1.w, a0o);
            a1o = fmaf(w1.x, p1.x, a1o); a1o = fmaf(w1.y, p1.y, a1o);
            a1o = fmaf(w1.z, p1.z, a1o); a1o = fmaf(w1.w, p1.w, a1o);
        }
        s.gates[b0][gg_][jj_] = gp0 + s.tagc[s.pred[b0]][r] + a0e + a0o;
        s.gates[b1][gg_][jj_] = gp1 + s.tagc[s.pred[b1]][r] + a1e + a1o;
        __syncthreads();

        const int par = t & 1;
        // ---- LSTM elementwise on own j-slice + broadcast h_new to the cluster ----
        if (tid < NB * JS) {
            int eb = tid >> 5, ej = tid & 31;
            float ig = s.gates[eb][0][ej], fg = s.gates[eb][1][ej];
            float gv = s.gates[eb][2][ej], og = s.gates[eb][3][ej];
            float cold = s.c[eb][ej];
            float cn = sigf(fg) * cold + sigf(ig) * tanhf(gv);
            float hn = sigf(og) * tanhf(cn);
            float mi = mask[(bbase + eb) * T_ + t];
            s.c[eb][ej] = mi * cn + (1.f - mi) * cold;
            uint32_t addr = (uint32_t)__cvta_generic_to_shared(
                &s.hnew[par][eb][(int)rank * JS + ej]);
            #pragma unroll
            for (int dst = 0; dst < CLUSTER; ++dst)
                st_cluster_f32(addr, (uint32_t)dst, hn);
        }
        cluster_sync_();   // arrive=release orders the DSMEM stores; wait=acquire

        // ---- scores (each CTA redundantly; 8 warps = 4 batches x 2 tags) ----
        {
            int w = tid >> 5, lane = tid & 31;
            int sb = w >> 1, sk = w & 1;
            float acc = 0.f;
            #pragma unroll
            for (int e = 0; e < 8; ++e)
                acc = fmaf(s.waffh[sk][lane + 32 * e], s.hnew[par][sb][lane + 32 * e], acc);
            #pragma unroll
            for (int o = 16; o > 0; o >>= 1) acc += __shfl_xor_sync(0xffffffffu, acc, o);
            if (lane == 0)
                s.score[sb][sk] = acc + __ldg(&g_sp[((size_t)(bbase + sb) * T_ + t) * 2 + sk]);
        }
        // ---- h update (masked), concurrent with score phase (disjoint writes) ----
        #pragma unroll
        for (int i = 0; i < 4; ++i) {
            int idx = tid + i * 256;
            int ub = idx >> 8, uj = idx & 255;
            float mi = mask[(bbase + ub) * T_ + t];
            s.h[ub][uj] = mi * s.hnew[par][ub][uj] + (1.f - mi) * s.h[ub][uj];
        }
        __syncthreads();

        // ---- pred + log_softmax output ----
        if (tid < NB) {
            float s0 = s.score[tid][0], s1 = s.score[tid][1];
            s.pred[tid] = (s1 > s0) ? 1 : 0;
            if (rank == 0) {
                float mx = fmaxf(s0, s1);
                float lse = mx + logf(expf(s0 - mx) + expf(s1 - mx));
                size_t o = ((size_t)(bbase + tid) * T_ + t) * 2;
                out[o]     = s0 - lse;
                out[o + 1] = s1 - lse;
            }
        }
        __syncthreads();
    }
}

// ---------------- launch ----------------
extern "C" void kernel_launch(void* const* d_in, const int* in_sizes, int n_in,
                              void* d_out, int out_size) {
    const float* sents  = (const float*)d_in[0];
    const float* mask   = (const float*)d_in[1];
    const float* Wih    = (const float*)d_in[2];
    const float* Whh    = (const float*)d_in[3];
    const float* bih    = (const float*)d_in[4];
    const float* bhh    = (const float*)d_in[5];
    const float* Waff   = (const float*)d_in[6];
    const float* baff   = (const float*)d_in[7];
    const float* tag_em = (const float*)d_in[8];
    float* out = (float*)d_out;

    cudaFuncSetAttribute(rnn_kernel, cudaFuncAttributeMaxDynamicSharedMemorySize,
                         (int)sizeof(RnnSmem));

    prep_kernel<<<KIN + 1, 256>>>(Wih, bih, bhh, tag_em);
    sgemm_kernel<<<dim3(G4 / 128, (B_ * T_) / 128), 256>>>(sents);
    spre_kernel<<<(B_ * T_) / 8, 256>>>(sents, Waff, baff);
    rnn_kernel<<<16 * CLUSTER, 256, sizeof(RnnSmem)>>>(mask, Whh, Waff, out);
}

// round 3
// speedup vs baseline: 1.5168x; 1.5168x over previous
#include <cuda_runtime.h>
#include <cuda_bf16.h>
#include <cstdint>
#include <cstddef>

#define B_    64
#define T_    512
#define H_    256
#define G4    1024
#define KIN   768
#define CLUSTER 8
#define NB    4
#define JS    32
#define RROWS 128

#define KC    32          // bf16 K per chunk
#define NCH   24          // 768/32
#define NSTG  4
#define ROWB  80          // padded smem row stride (bytes) for 32 bf16
#define TILE_B (128 * ROWB)      // 10240
#define STG_B  (4 * TILE_B)      // 40960
#define GSM_TOTAL (NSTG * STG_B) // 163840

// ---------------- scratch (static device globals) ----------------
__device__ float g_gp[(size_t)B_ * T_ * G4];
__device__ float g_sp[B_ * T_ * 2];
__device__ float g_bias[G4];
__device__ float g_tagc[3 * G4];
__device__ __align__(16) __nv_bfloat16 g_Ahi[(size_t)B_ * T_ * KIN];
__device__ __align__(16) __nv_bfloat16 g_Alo[(size_t)B_ * T_ * KIN];
__device__ __align__(16) __nv_bfloat16 g_Bhi[G4 * KIN];
__device__ __align__(16) __nv_bfloat16 g_Blo[G4 * KIN];

// ---------------- PTX helpers (base sm_103 only) ----------------
__device__ __forceinline__ uint32_t smem_u32(const void* p) {
    uint32_t a;
    asm("{ .reg .u64 t; cvta.to.shared.u64 t, %1; cvt.u32.u64 %0, t; }" : "=r"(a) : "l"(p));
    return a;
}
__device__ __forceinline__ uint32_t ctarank_() {
    uint32_t r; asm("mov.u32 %0, %%cluster_ctarank;" : "=r"(r)); return r;
}
__device__ __forceinline__ void cluster_sync_() {
    asm volatile("barrier.cluster.arrive.aligned;\n\tbarrier.cluster.wait.aligned;" ::: "memory");
}
__device__ __forceinline__ void st_cluster_f32(uint32_t saddr, uint32_t dst, float v) {
    asm volatile(
        "{\n\t.reg .b32 ra;\n\t"
        "mapa.shared::cluster.u32 ra, %0, %1;\n\t"
        "st.shared::cluster.f32 [ra], %2;\n\t}"
        :: "r"(saddr), "r"(dst), "f"(v) : "memory");
}
__device__ __forceinline__ void cp16(uint32_t dst, const void* src) {
    asm volatile("cp.async.cg.shared.global [%0], [%1], 16;" :: "r"(dst), "l"(src));
}
#define CP_COMMIT() asm volatile("cp.async.commit_group;" ::: "memory")
#define CP_WAIT1()  asm volatile("cp.async.wait_group 1;" ::: "memory")

__device__ __forceinline__ void ldsm4(uint32_t* r, uint32_t addr) {
    asm volatile("ldmatrix.sync.aligned.m8n8.x4.shared.b16 {%0,%1,%2,%3}, [%4];"
                 : "=r"(r[0]), "=r"(r[1]), "=r"(r[2]), "=r"(r[3]) : "r"(addr));
}
__device__ __forceinline__ void mma16816(float* c, const uint32_t* a, const uint32_t* b) {
    asm volatile(
        "mma.sync.aligned.m16n8k16.row.col.f32.bf16.bf16.f32 "
        "{%0,%1,%2,%3}, {%4,%5,%6,%7}, {%8,%9}, {%0,%1,%2,%3};"
        : "+f"(c[0]), "+f"(c[1]), "+f"(c[2]), "+f"(c[3])
        : "r"(a[0]), "r"(a[1]), "r"(a[2]), "r"(a[3]), "r"(b[0]), "r"(b[1]));
}

// ---------------- conversion: fp32 -> bf16 hi/lo ----------------
__global__ __launch_bounds__(256) void convA_kernel(const float* __restrict__ A) {
    size_t i4 = (size_t)blockIdx.x * 256 + threadIdx.x;
    float4 v = *(const float4*)(A + i4 * 4);
    __nv_bfloat16 hx = __float2bfloat16_rn(v.x), hy = __float2bfloat16_rn(v.y);
    __nv_bfloat16 hz = __float2bfloat16_rn(v.z), hw = __float2bfloat16_rn(v.w);
    __nv_bfloat16 lx = __float2bfloat16_rn(v.x - __bfloat162float(hx));
    __nv_bfloat16 ly = __float2bfloat16_rn(v.y - __bfloat162float(hy));
    __nv_bfloat16 lz = __float2bfloat16_rn(v.z - __bfloat162float(hz));
    __nv_bfloat16 lw = __float2bfloat16_rn(v.w - __bfloat162float(hw));
    __nv_bfloat16 hv[4] = {hx, hy, hz, hw};
    __nv_bfloat16 lv[4] = {lx, ly, lz, lw};
    ((uint2*)g_Ahi)[i4] = *(uint2*)hv;
    ((uint2*)g_Alo)[i4] = *(uint2*)lv;
}

__global__ __launch_bounds__(256) void convB_kernel(const float* __restrict__ Wih) {
    size_t i4 = (size_t)blockIdx.x * 256 + threadIdx.x;
    size_t e = i4 * 4;
    int n = (int)(e / KIN), k = (int)(e % KIN);
    float4 v = *(const float4*)(Wih + (size_t)n * 800 + 32 + k);
    __nv_bfloat16 hx = __float2bfloat16_rn(v.x), hy = __float2bfloat16_rn(v.y);
    __nv_bfloat16 hz = __float2bfloat16_rn(v.z), hw = __float2bfloat16_rn(v.w);
    __nv_bfloat16 lx = __float2bfloat16_rn(v.x - __bfloat162float(hx));
    __nv_bfloat16 ly = __float2bfloat16_rn(v.y - __bfloat162float(hy));
    __nv_bfloat16 lz = __float2bfloat16_rn(v.z - __bfloat162float(hz));
    __nv_bfloat16 lw = __float2bfloat16_rn(v.w - __bfloat162float(hw));
    __nv_bfloat16 hv[4] = {hx, hy, hz, hw};
    __nv_bfloat16 lv[4] = {lx, ly, lz, lw};
    ((uint2*)g_Bhi)[i4] = *(uint2*)hv;
    ((uint2*)g_Blo)[i4] = *(uint2*)lv;
}

// ---------------- prep ----------------
__global__ void prep_kernel(const float* __restrict__ Wih,
                            const float* __restrict__ bih,
                            const float* __restrict__ bhh,
                            const float* __restrict__ tag_em) {
    int n = blockIdx.x * 256 + threadIdx.x;
    if (n >= G4) return;
    g_bias[n] = bih[n] + bhh[n];
    float t0 = 0.f, t1 = 0.f;
    #pragma unroll
    for (int e = 0; e < 32; ++e) {
        float w = Wih[n * 800 + e];
        t0 = fmaf(tag_em[e], w, t0);
        t1 = fmaf(tag_em[32 + e], w, t1);
    }
    g_tagc[n] = t0;
    g_tagc[G4 + n] = t1;
    g_tagc[2 * G4 + n] = 0.f;
}

// ---------------- HMMA GEMM: g_gp = A @ B^T + bias (bf16x3) ----------------
// M=32768, N=1024, K=768. CTA tile 128x128, warp tile 64x32, Kc=32, 4-stage cp.async.
__global__ __launch_bounds__(256, 1) void gemm_kernel() {
    extern __shared__ char smem[];
    const uint32_t sb = smem_u32(smem);
    const int tid = threadIdx.x;
    const int wid = tid >> 5, lane = tid & 31;
    const int bn = blockIdx.x, bm = blockIdx.y;
    const int m0 = bm * 128, n0 = bn * 128;
    const int wm = (wid & 1) * 64;
    const int wn = (wid >> 1) * 32;

    // per-thread cp.async mapping (8 x 16B per stage)
    const __nv_bfloat16* srcp[8];
    uint32_t dsto[8];
    #pragma unroll
    for (int i = 0; i < 8; ++i) {
        int id = tid + i * 256;
        int tile = id >> 9, rem = id & 511;
        int row = rem >> 2, c4 = rem & 3;
        const __nv_bfloat16* base =
            (tile == 0) ? g_Ahi + (size_t)m0 * KIN :
            (tile == 1) ? g_Alo + (size_t)m0 * KIN :
            (tile == 2) ? g_Bhi + (size_t)n0 * KIN :
                          g_Blo + (size_t)n0 * KIN;
        srcp[i] = base + (size_t)row * KIN + c4 * 8;
        dsto[i] = (uint32_t)(tile * TILE_B + row * ROWB + c4 * 16);
    }

    float acc[4][4][4];
    #pragma unroll
    for (int a = 0; a < 4; ++a)
        #pragma unroll
        for (int b = 0; b < 4; ++b)
            #pragma unroll
            for (int q = 0; q < 4; ++q) acc[a][b][q] = 0.f;

    // fragment base offsets
    const uint32_t aoff = (uint32_t)((wm + (lane & 15)) * ROWB + (lane >> 4) * 16);
    const int brow = ((lane >> 4) & 1) * 8 + (lane & 7);
    const uint32_t boff = (uint32_t)((wn + brow) * ROWB + ((lane >> 3) & 1) * 16);

    // prologue: chunks 0 and 1
    #pragma unroll
    for (int c = 0; c < 2; ++c) {
        uint32_t stg = sb + (uint32_t)(c & (NSTG - 1)) * STG_B;
        #pragma unroll
        for (int i = 0; i < 8; ++i) cp16(stg + dsto[i], srcp[i] + c * KC);
        CP_COMMIT();
    }

    for (int c = 0; c < NCH; ++c) {
        CP_WAIT1();
        __syncthreads();
        // prefetch chunk c+2
        if (c + 2 < NCH) {
            uint32_t stg = sb + (uint32_t)((c + 2) & (NSTG - 1)) * STG_B;
            #pragma unroll
            for (int i = 0; i < 8; ++i) cp16(stg + dsto[i], srcp[i] + (c + 2) * KC);
        }
        CP_COMMIT();

        const uint32_t sbase = sb + (uint32_t)(c & (NSTG - 1)) * STG_B;
        const uint32_t sAhi = sbase, sAlo = sbase + TILE_B;
        const uint32_t sBhi = sbase + 2 * TILE_B, sBlo = sbase + 3 * TILE_B;

        #pragma unroll
        for (int ks = 0; ks < 2; ++ks) {
            const uint32_t ko = ks * 32;
            uint32_t ah[4][4], al[4][4], bh[2][4], bl[2][4];
            #pragma unroll
            for (int mi = 0; mi < 4; ++mi) ldsm4(ah[mi], sAhi + aoff + mi * 16 * ROWB + ko);
            #pragma unroll
            for (int nj = 0; nj < 2; ++nj) ldsm4(bh[nj], sBhi + boff + nj * 16 * ROWB + ko);
            #pragma unroll
            for (int mi = 0; mi < 4; ++mi)
                #pragma unroll
                for (int ni = 0; ni < 4; ++ni)
                    mma16816(acc[mi][ni], ah[mi], &bh[ni >> 1][(ni & 1) * 2]);
            #pragma unroll
            for (int nj = 0; nj < 2; ++nj) ldsm4(bl[nj], sBlo + boff + nj * 16 * ROWB + ko);
            #pragma unroll
            for (int mi = 0; mi < 4; ++mi)
                #pragma unroll
                for (int ni = 0; ni < 4; ++ni)
                    mma16816(acc[mi][ni], ah[mi], &bl[ni >> 1][(ni & 1) * 2]);
            #pragma unroll
            for (int mi = 0; mi < 4; ++mi) ldsm4(al[mi], sAlo + aoff + mi * 16 * ROWB + ko);
            #pragma unroll
            for (int mi = 0; mi < 4; ++mi)
                #pragma unroll
                for (int ni = 0; ni < 4; ++ni)
                    mma16816(acc[mi][ni], al[mi], &bh[ni >> 1][(ni & 1) * 2]);
        }
        __syncthreads();
    }

    // epilogue: direct stores with bias
    const int rowb = lane >> 2, col2 = (lane & 3) * 2;
    #pragma unroll
    for (int mi = 0; mi < 4; ++mi) {
        const int gr = m0 + wm + mi * 16 + rowb;
        #pragma unroll
        for (int ni = 0; ni < 4; ++ni) {
            const int gc = n0 + wn + ni * 8 + col2;
            float b0v = __ldg(&g_bias[gc]), b1v = __ldg(&g_bias[gc + 1]);
            float2 v0 = make_float2(acc[mi][ni][0] + b0v, acc[mi][ni][1] + b1v);
            float2 v1 = make_float2(acc[mi][ni][2] + b0v, acc[mi][ni][3] + b1v);
            *(float2*)&g_gp[(size_t)gr * G4 + gc] = v0;
            *(float2*)&g_gp[(size_t)(gr + 8) * G4 + gc] = v1;
        }
    }
}

// ---------------- score_pre ----------------
__global__ __launch_bounds__(256) void spre_kernel(const float* __restrict__ sents,
                                                   const float* __restrict__ Waff,
                                                   const float* __restrict__ baff) {
    int warp = (blockIdx.x * 256 + threadIdx.x) >> 5;
    int lane = threadIdx.x & 31;
    if (warp >= B_ * T_) return;
    const float4* a  = (const float4*)(sents + (size_t)warp * KIN);
    const float4* w0 = (const float4*)(Waff + 256);
    const float4* w1 = (const float4*)(Waff + G4 + 256);
    float s0 = 0.f, s1 = 0.f;
    #pragma unroll
    for (int i = lane; i < KIN / 4; i += 32) {
        float4 av = a[i], v0 = w0[i], v1 = w1[i];
        s0 = fmaf(av.x, v0.x, s0); s0 = fmaf(av.y, v0.y, s0);
        s0 = fmaf(av.z, v0.z, s0); s0 = fmaf(av.w, v0.w, s0);
        s1 = fmaf(av.x, v1.x, s1); s1 = fmaf(av.y, v1.y, s1);
        s1 = fmaf(av.z, v1.z, s1); s1 = fmaf(av.w, v1.w, s1);
    }
    #pragma unroll
    for (int o = 16; o > 0; o >>= 1) {
        s0 += __shfl_xor_sync(0xffffffffu, s0, o);
        s1 += __shfl_xor_sync(0xffffffffu, s1, o);
    }
    if (lane == 0) {
        g_sp[(size_t)warp * 2]     = s0 + baff[0];
        g_sp[(size_t)warp * 2 + 1] = s1 + baff[1];
    }
}

// ---------------- recurrence: register-resident Whh ----------------
struct RnnSmem {
    float h[NB][H_];
    float hnew[2][NB][H_];
    float c[NB][JS];
    float gates[NB][4][JS];
    float part[2][128][NB];
    float tagc[3][RROWS];
    float waffh[2][H_];
    float score[NB][2];
    int   pred[NB];
};

__device__ __forceinline__ float sigf(float x) { return 1.f / (1.f + expf(-x)); }

__global__ void __cluster_dims__(CLUSTER, 1, 1) __launch_bounds__(256, 1)
rnn_kernel(const float* __restrict__ mask,
           const float* __restrict__ Whh,
           const float* __restrict__ Waff,
           float* __restrict__ out) {
    extern __shared__ unsigned char smem_raw[];
    RnnSmem& s = *reinterpret_cast<RnnSmem*>(smem_raw);

    const int tid = threadIdx.x;
    const uint32_t rank = ctarank_();
    const int cid = blockIdx.x >> 3;
    const int bbase = cid * NB;

    const int r = tid & 127;
    const int half = tid >> 7;
    const int grow = (r >> 5) * 256 + (int)rank * JS + (r & 31);

    float4 wreg[32];
    {
        const float4* wsrc = (const float4*)(Whh + (size_t)grow * H_ + half * 128);
        #pragma unroll
        for (int i = 0; i < 32; ++i) wreg[i] = wsrc[i];
    }

    for (int rr = tid; rr < RROWS; rr += 256) {
        int gr = (rr >> 5) * 256 + (int)rank * JS + (rr & 31);
        s.tagc[0][rr] = g_tagc[gr];
        s.tagc[1][rr] = g_tagc[G4 + gr];
        s.tagc[2][rr] = 0.f;
    }
    for (int i = tid; i < 2 * H_; i += 256) s.waffh[i >> 8][i & 255] = Waff[(i >> 8) * G4 + (i & 255)];
    for (int i = tid; i < NB * H_; i += 256) s.h[i >> 8][i & 255] = 0.f;
    for (int i = tid; i < NB * JS; i += 256) s.c[i >> 5][i & 31] = 0.f;
    if (tid < NB) s.pred[tid] = 2;
    __syncthreads();

    for (int t = 0; t < T_; ++t) {
        float gp[NB];
        if (tid < 128) {
            #pragma unroll
            for (int b = 0; b < NB; ++b)
                gp[b] = __ldg(&g_gp[((size_t)(bbase + b) * T_ + t) * G4 + grow]);
        }

        float a2[NB];
        #pragma unroll
        for (int b = 0; b < NB; ++b) {
            const float4* x4 = (const float4*)&s.h[b][half * 128];
            float ae = 0.f, ao = 0.f;
            #pragma unroll
            for (int i = 0; i < 32; i += 2) {
                float4 w0 = wreg[i], w1 = wreg[i + 1];
                float4 q0 = x4[i],  q1 = x4[i + 1];
                ae = fmaf(w0.x, q0.x, ae); ae = fmaf(w0.y, q0.y, ae);
                ae = fmaf(w0.z, q0.z, ae); ae = fmaf(w0.w, q0.w, ae);
                ao = fmaf(w1.x, q1.x, ao); ao = fmaf(w1.y, q1.y, ao);
                ao = fmaf(w1.z, q1.z, ao); ao = fmaf(w1.w, q1.w, ao);
            }
            a2[b] = ae + ao;
        }
        *(float4*)&s.part[half][r][0] = make_float4(a2[0], a2[1], a2[2], a2[3]);
        __syncthreads();

        if (tid < 128) {
            float4 p0 = *(const float4*)&s.part[0][r][0];
            float4 p1 = *(const float4*)&s.part[1][r][0];
            const int gg = r >> 5, jj = r & 31;
            s.gates[0][gg][jj] = gp[0] + s.tagc[s.pred[0]][r] + p0.x + p1.x;
            s.gates[1][gg][jj] = gp[1] + s.tagc[s.pred[1]][r] + p0.y + p1.y;
            s.gates[2][gg][jj] = gp[2] + s.tagc[s.pred[2]][r] + p0.z + p1.z;
            s.gates[3][gg][jj] = gp[3] + s.tagc[s.pred[3]][r] + p0.w + p1.w;
        }
        __syncthreads();

        const int par = t & 1;
        if (tid < NB * JS) {
            int eb = tid >> 5, ej = tid & 31;
            float ig = s.gates[eb][0][ej], fg = s.gates[eb][1][ej];
            float gv = s.gates[eb][2][ej], og = s.gates[eb][3][ej];
            float cold = s.c[eb][ej];
            float cn = sigf(fg) * cold + sigf(ig) * tanhf(gv);
            float hn = sigf(og) * tanhf(cn);
            float mi = mask[(bbase + eb) * T_ + t];
            s.c[eb][ej] = mi * cn + (1.f - mi) * cold;
            uint32_t addr = (uint32_t)__cvta_generic_to_shared(
                &s.hnew[par][eb][(int)rank * JS + ej]);
            #pragma unroll
            for (int dst = 0; dst < CLUSTER; ++dst)
                st_cluster_f32(addr, (uint32_t)dst, hn);
        }
        cluster_sync_();

        {
            int w = tid >> 5, lane = tid & 31;
            int sbv = w >> 1, sk = w & 1;
            float av = 0.f;
            #pragma unroll
            for (int e = 0; e < 8; ++e)
                av = fmaf(s.waffh[sk][lane + 32 * e], s.hnew[par][sbv][lane + 32 * e], av);
            #pragma unroll
            for (int o = 16; o > 0; o >>= 1) av += __shfl_xor_sync(0xffffffffu, av, o);
            if (lane == 0)
                s.score[sbv][sk] = av + __ldg(&g_sp[((size_t)(bbase + sbv) * T_ + t) * 2 + sk]);
        }
        #pragma unroll
        for (int i = 0; i < 4; ++i) {
            int idx = tid + i * 256;
            int ub = idx >> 8, uj = idx & 255;
            float mi = mask[(bbase + ub) * T_ + t];
            s.h[ub][uj] = mi * s.hnew[par][ub][uj] + (1.f - mi) * s.h[ub][uj];
        }
        __syncthreads();

        if (tid < NB) {
            float s0 = s.score[tid][0], s1 = s.score[tid][1];
            s.pred[tid] = (s1 > s0) ? 1 : 0;
            if (rank == 0) {
                float mx = fmaxf(s0, s1);
                float lse = mx + logf(expf(s0 - mx) + expf(s1 - mx));
                size_t o = ((size_t)(bbase + tid) * T_ + t) * 2;
                out[o]     = s0 - lse;
                out[o + 1] = s1 - lse;
            }
        }
        __syncthreads();
    }
}

// ---------------- launch ----------------
extern "C" void kernel_launch(void* const* d_in, const int* in_sizes, int n_in,
                              void* d_out, int out_size) {
    const float* sents  = (const float*)d_in[0];
    const float* mask   = (const float*)d_in[1];
    const float* Wih    = (const float*)d_in[2];
    const float* Whh    = (const float*)d_in[3];
    const float* bih    = (const float*)d_in[4];
    const float* bhh    = (const float*)d_in[5];
    const float* Waff   = (const float*)d_in[6];
    const float* baff   = (const float*)d_in[7];
    const float* tag_em = (const float*)d_in[8];
    float* out = (float*)d_out;

    cudaFuncSetAttribute(gemm_kernel, cudaFuncAttributeMaxDynamicSharedMemorySize, GSM_TOTAL);
    cudaFuncSetAttribute(rnn_kernel, cudaFuncAttributeMaxDynamicSharedMemorySize,
                         (int)sizeof(RnnSmem));

    convA_kernel<<<(B_ * T_ * KIN) / (256 * 4), 256>>>(sents);
    convB_kernel<<<(G4 * KIN) / (256 * 4), 256>>>(Wih);
    prep_kernel<<<4, 256>>>(Wih, bih, bhh, tag_em);
    spre_kernel<<<(B_ * T_) / 8, 256>>>(sents, Waff, baff);
    gemm_kernel<<<dim3(G4 / 128, (B_ * T_) / 128), 256, GSM_TOTAL>>>();
    rnn_kernel<<<16 * CLUSTER, 256, sizeof(RnnSmem)>>>(mask, Whh, Waff, out);
}

// round 4
// speedup vs baseline: 1.6415x; 1.0822x over previous
#include <cuda_runtime.h>
#include <cuda_bf16.h>
#include <cstdint>
#include <cstddef>

#define B_    64
#define T_    512
#define H_    256
#define G4    1024
#define KIN   768
#define CLUSTER 8
#define NB    4
#define JS    32
#define RROWS 128

#define KC    32
#define NCH   24
#define NSTG  4
#define ROWB  80
#define TILE_B (128 * ROWB)
#define STG_B  (4 * TILE_B)
#define GSM_TOTAL (NSTG * STG_B)

// ---------------- scratch ----------------
__device__ float g_gp[(size_t)B_ * T_ * G4];
__device__ float g_sp[B_ * T_ * 2];
__device__ float g_bias[G4];
__device__ float g_tagc[3 * G4];
__device__ __align__(16) __nv_bfloat16 g_Ahi[(size_t)B_ * T_ * KIN];
__device__ __align__(16) __nv_bfloat16 g_Alo[(size_t)B_ * T_ * KIN];
__device__ __align__(16) __nv_bfloat16 g_Bhi[G4 * KIN];
__device__ __align__(16) __nv_bfloat16 g_Blo[G4 * KIN];

// ---------------- PTX helpers (base sm_103 only) ----------------
__device__ __forceinline__ uint32_t smem_u32(const void* p) {
    uint32_t a;
    asm("{ .reg .u64 t; cvta.to.shared.u64 t, %1; cvt.u32.u64 %0, t; }" : "=r"(a) : "l"(p));
    return a;
}
__device__ __forceinline__ uint32_t ctarank_() {
    uint32_t r; asm("mov.u32 %0, %%cluster_ctarank;" : "=r"(r)); return r;
}
__device__ __forceinline__ void cluster_sync_() {
    asm volatile("barrier.cluster.arrive.aligned;\n\tbarrier.cluster.wait.aligned;" ::: "memory");
}
__device__ __forceinline__ void st_cluster_f32(uint32_t saddr, uint32_t dst, float v) {
    asm volatile(
        "{\n\t.reg .b32 ra;\n\t"
        "mapa.shared::cluster.u32 ra, %0, %1;\n\t"
        "st.shared::cluster.f32 [ra], %2;\n\t}"
        :: "r"(saddr), "r"(dst), "f"(v) : "memory");
}
__device__ __forceinline__ void cp16(uint32_t dst, const void* src) {
    asm volatile("cp.async.cg.shared.global [%0], [%1], 16;" :: "r"(dst), "l"(src));
}
#define CP_COMMIT() asm volatile("cp.async.commit_group;" ::: "memory")
#define CP_WAIT1()  asm volatile("cp.async.wait_group 1;" ::: "memory")

__device__ __forceinline__ void ldsm4(uint32_t* r, uint32_t addr) {
    asm volatile("ldmatrix.sync.aligned.m8n8.x4.shared.b16 {%0,%1,%2,%3}, [%4];"
                 : "=r"(r[0]), "=r"(r[1]), "=r"(r[2]), "=r"(r[3]) : "r"(addr));
}
__device__ __forceinline__ void mma16816(float* c, const uint32_t* a, const uint32_t* b) {
    asm volatile(
        "mma.sync.aligned.m16n8k16.row.col.f32.bf16.bf16.f32 "
        "{%0,%1,%2,%3}, {%4,%5,%6,%7}, {%8,%9}, {%0,%1,%2,%3};"
        : "+f"(c[0]), "+f"(c[1]), "+f"(c[2]), "+f"(c[3])
        : "r"(a[0]), "r"(a[1]), "r"(a[2]), "r"(a[3]), "r"(b[0]), "r"(b[1]));
}
// packed f32x2 FMA (sm_100+ base feature)
__device__ __forceinline__ void fma2(unsigned long long& d, unsigned long long a,
                                     unsigned long long b) {
    asm("fma.rn.f32x2 %0, %1, %2, %0;" : "+l"(d) : "l"(a), "l"(b));
}
__device__ __forceinline__ float2 unpack64(unsigned long long v) {
    float2 r;
    asm("mov.b64 {%0, %1}, %2;" : "=f"(r.x), "=f"(r.y) : "l"(v));
    return r;
}

// ---------------- conversion: fp32 -> bf16 hi/lo ----------------
__global__ __launch_bounds__(256) void convA_kernel(const float* __restrict__ A) {
    size_t i4 = (size_t)blockIdx.x * 256 + threadIdx.x;
    float4 v = *(const float4*)(A + i4 * 4);
    __nv_bfloat16 hx = __float2bfloat16_rn(v.x), hy = __float2bfloat16_rn(v.y);
    __nv_bfloat16 hz = __float2bfloat16_rn(v.z), hw = __float2bfloat16_rn(v.w);
    __nv_bfloat16 lx = __float2bfloat16_rn(v.x - __bfloat162float(hx));
    __nv_bfloat16 ly = __float2bfloat16_rn(v.y - __bfloat162float(hy));
    __nv_bfloat16 lz = __float2bfloat16_rn(v.z - __bfloat162float(hz));
    __nv_bfloat16 lw = __float2bfloat16_rn(v.w - __bfloat162float(hw));
    __nv_bfloat16 hv[4] = {hx, hy, hz, hw};
    __nv_bfloat16 lv[4] = {lx, ly, lz, lw};
    ((uint2*)g_Ahi)[i4] = *(uint2*)hv;
    ((uint2*)g_Alo)[i4] = *(uint2*)lv;
}

__global__ __launch_bounds__(256) void convB_kernel(const float* __restrict__ Wih) {
    size_t i4 = (size_t)blockIdx.x * 256 + threadIdx.x;
    size_t e = i4 * 4;
    int n = (int)(e / KIN), k = (int)(e % KIN);
    float4 v = *(const float4*)(Wih + (size_t)n * 800 + 32 + k);
    __nv_bfloat16 hx = __float2bfloat16_rn(v.x), hy = __float2bfloat16_rn(v.y);
    __nv_bfloat16 hz = __float2bfloat16_rn(v.z), hw = __float2bfloat16_rn(v.w);
    __nv_bfloat16 lx = __float2bfloat16_rn(v.x - __bfloat162float(hx));
    __nv_bfloat16 ly = __float2bfloat16_rn(v.y - __bfloat162float(hy));
    __nv_bfloat16 lz = __float2bfloat16_rn(v.z - __bfloat162float(hz));
    __nv_bfloat16 lw = __float2bfloat16_rn(v.w - __bfloat162float(hw));
    __nv_bfloat16 hv[4] = {hx, hy, hz, hw};
    __nv_bfloat16 lv[4] = {lx, ly, lz, lw};
    ((uint2*)g_Bhi)[i4] = *(uint2*)hv;
    ((uint2*)g_Blo)[i4] = *(uint2*)lv;
}

// ---------------- prep ----------------
__global__ void prep_kernel(const float* __restrict__ Wih,
                            const float* __restrict__ bih,
                            const float* __restrict__ bhh,
                            const float* __restrict__ tag_em) {
    int n = blockIdx.x * 256 + threadIdx.x;
    if (n >= G4) return;
    g_bias[n] = bih[n] + bhh[n];
    float t0 = 0.f, t1 = 0.f;
    #pragma unroll
    for (int e = 0; e < 32; ++e) {
        float w = Wih[n * 800 + e];
        t0 = fmaf(tag_em[e], w, t0);
        t1 = fmaf(tag_em[32 + e], w, t1);
    }
    g_tagc[n] = t0;
    g_tagc[G4 + n] = t1;
    g_tagc[2 * G4 + n] = 0.f;
}

// ---------------- HMMA GEMM (unchanged from round 3) ----------------
__global__ __launch_bounds__(256, 1) void gemm_kernel() {
    extern __shared__ char smem[];
    const uint32_t sb = smem_u32(smem);
    const int tid = threadIdx.x;
    const int wid = tid >> 5, lane = tid & 31;
    const int bn = blockIdx.x, bm = blockIdx.y;
    const int m0 = bm * 128, n0 = bn * 128;
    const int wm = (wid & 1) * 64;
    const int wn = (wid >> 1) * 32;

    const __nv_bfloat16* srcp[8];
    uint32_t dsto[8];
    #pragma unroll
    for (int i = 0; i < 8; ++i) {
        int id = tid + i * 256;
        int tile = id >> 9, rem = id & 511;
        int row = rem >> 2, c4 = rem & 3;
        const __nv_bfloat16* base =
            (tile == 0) ? g_Ahi + (size_t)m0 * KIN :
            (tile == 1) ? g_Alo + (size_t)m0 * KIN :
            (tile == 2) ? g_Bhi + (size_t)n0 * KIN :
                          g_Blo + (size_t)n0 * KIN;
        srcp[i] = base + (size_t)row * KIN + c4 * 8;
        dsto[i] = (uint32_t)(tile * TILE_B + row * ROWB + c4 * 16);
    }

    float acc[4][4][4];
    #pragma unroll
    for (int a = 0; a < 4; ++a)
        #pragma unroll
        for (int b = 0; b < 4; ++b)
            #pragma unroll
            for (int q = 0; q < 4; ++q) acc[a][b][q] = 0.f;

    const uint32_t aoff = (uint32_t)((wm + (lane & 15)) * ROWB + (lane >> 4) * 16);
    const int brow = ((lane >> 4) & 1) * 8 + (lane & 7);
    const uint32_t boff = (uint32_t)((wn + brow) * ROWB + ((lane >> 3) & 1) * 16);

    #pragma unroll
    for (int c = 0; c < 2; ++c) {
        uint32_t stg = sb + (uint32_t)(c & (NSTG - 1)) * STG_B;
        #pragma unroll
        for (int i = 0; i < 8; ++i) cp16(stg + dsto[i], srcp[i] + c * KC);
        CP_COMMIT();
    }

    for (int c = 0; c < NCH; ++c) {
        CP_WAIT1();
        __syncthreads();
        if (c + 2 < NCH) {
            uint32_t stg = sb + (uint32_t)((c + 2) & (NSTG - 1)) * STG_B;
            #pragma unroll
            for (int i = 0; i < 8; ++i) cp16(stg + dsto[i], srcp[i] + (c + 2) * KC);
        }
        CP_COMMIT();

        const uint32_t sbase = sb + (uint32_t)(c & (NSTG - 1)) * STG_B;
        const uint32_t sAhi = sbase, sAlo = sbase + TILE_B;
        const uint32_t sBhi = sbase + 2 * TILE_B, sBlo = sbase + 3 * TILE_B;

        #pragma unroll
        for (int ks = 0; ks < 2; ++ks) {
            const uint32_t ko = ks * 32;
            uint32_t ah[4][4], al[4][4], bh[2][4], bl[2][4];
            #pragma unroll
            for (int mi = 0; mi < 4; ++mi) ldsm4(ah[mi], sAhi + aoff + mi * 16 * ROWB + ko);
            #pragma unroll
            for (int nj = 0; nj < 2; ++nj) ldsm4(bh[nj], sBhi + boff + nj * 16 * ROWB + ko);
            #pragma unroll
            for (int mi = 0; mi < 4; ++mi)
                #pragma unroll
                for (int ni = 0; ni < 4; ++ni)
                    mma16816(acc[mi][ni], ah[mi], &bh[ni >> 1][(ni & 1) * 2]);
            #pragma unroll
            for (int nj = 0; nj < 2; ++nj) ldsm4(bl[nj], sBlo + boff + nj * 16 * ROWB + ko);
            #pragma unroll
            for (int mi = 0; mi < 4; ++mi)
                #pragma unroll
                for (int ni = 0; ni < 4; ++ni)
                    mma16816(acc[mi][ni], ah[mi], &bl[ni >> 1][(ni & 1) * 2]);
            #pragma unroll
            for (int mi = 0; mi < 4; ++mi) ldsm4(al[mi], sAlo + aoff + mi * 16 * ROWB + ko);
            #pragma unroll
            for (int mi = 0; mi < 4; ++mi)
                #pragma unroll
                for (int ni = 0; ni < 4; ++ni)
                    mma16816(acc[mi][ni], al[mi], &bh[ni >> 1][(ni & 1) * 2]);
        }
        __syncthreads();
    }

    const int rowb2 = lane >> 2, col2 = (lane & 3) * 2;
    #pragma unroll
    for (int mi = 0; mi < 4; ++mi) {
        const int gr = m0 + wm + mi * 16 + rowb2;
        #pragma unroll
        for (int ni = 0; ni < 4; ++ni) {
            const int gc = n0 + wn + ni * 8 + col2;
            float b0v = __ldg(&g_bias[gc]), b1v = __ldg(&g_bias[gc + 1]);
            float2 v0 = make_float2(acc[mi][ni][0] + b0v, acc[mi][ni][1] + b1v);
            float2 v1 = make_float2(acc[mi][ni][2] + b0v, acc[mi][ni][3] + b1v);
            *(float2*)&g_gp[(size_t)gr * G4 + gc] = v0;
            *(float2*)&g_gp[(size_t)(gr + 8) * G4 + gc] = v1;
        }
    }
}

// ---------------- score_pre ----------------
__global__ __launch_bounds__(256) void spre_kernel(const float* __restrict__ sents,
                                                   const float* __restrict__ Waff,
                                                   const float* __restrict__ baff) {
    int warp = (blockIdx.x * 256 + threadIdx.x) >> 5;
    int lane = threadIdx.x & 31;
    if (warp >= B_ * T_) return;
    const float4* a  = (const float4*)(sents + (size_t)warp * KIN);
    const float4* w0 = (const float4*)(Waff + 256);
    const float4* w1 = (const float4*)(Waff + G4 + 256);
    float s0 = 0.f, s1 = 0.f;
    #pragma unroll
    for (int i = lane; i < KIN / 4; i += 32) {
        float4 av = a[i], v0 = w0[i], v1 = w1[i];
        s0 = fmaf(av.x, v0.x, s0); s0 = fmaf(av.y, v0.y, s0);
        s0 = fmaf(av.z, v0.z, s0); s0 = fmaf(av.w, v0.w, s0);
        s1 = fmaf(av.x, v1.x, s1); s1 = fmaf(av.y, v1.y, s1);
        s1 = fmaf(av.z, v1.z, s1); s1 = fmaf(av.w, v1.w, s1);
    }
    #pragma unroll
    for (int o = 16; o > 0; o >>= 1) {
        s0 += __shfl_xor_sync(0xffffffffu, s0, o);
        s1 += __shfl_xor_sync(0xffffffffu, s1, o);
    }
    if (lane == 0) {
        g_sp[(size_t)warp * 2]     = s0 + baff[0];
        g_sp[(size_t)warp * 2 + 1] = s1 + baff[1];
    }
}

// ---------------- recurrence: f32x2 matvec, 3 barriers/step ----------------
struct RnnSmem {
    float h[NB][H_];           // masked h_{t-1}
    float hnew[2][NB][H_];     // double-buffered unmasked h_t
    float part[2][128][NB];    // split-K partials
    float tagc[3][RROWS];
    float waffh[2][H_];
    float maskS[NB][T_];       // preloaded mask
    float score[NB][2];
    int   pred[NB];
};

__device__ __forceinline__ float sigf(float x) { return 1.f / (1.f + expf(-x)); }

__global__ void __cluster_dims__(CLUSTER, 1, 1) __launch_bounds__(256, 1)
rnn_kernel(const float* __restrict__ mask,
           const float* __restrict__ Whh,
           const float* __restrict__ Waff,
           float* __restrict__ out) {
    extern __shared__ unsigned char smem_raw[];
    RnnSmem& s = *reinterpret_cast<RnnSmem*>(smem_raw);

    const int tid = threadIdx.x;
    const int wid = tid >> 5, lane = tid & 31;
    const uint32_t rank = ctarank_();
    const int cid = blockIdx.x >> 3;
    const int bbase = cid * NB;

    const int r = tid & 127;
    const int half = tid >> 7;
    const int grow = (r >> 5) * 256 + (int)rank * JS + (r & 31);

    // weights in registers as f32x2 pairs: 128 floats = 32 ulonglong2
    ulonglong2 wreg2[32];
    {
        const ulonglong2* wsrc = (const ulonglong2*)(Whh + (size_t)grow * H_ + half * 128);
        #pragma unroll
        for (int i = 0; i < 32; ++i) wreg2[i] = wsrc[i];
    }

    for (int rr = tid; rr < RROWS; rr += 256) {
        int gr = (rr >> 5) * 256 + (int)rank * JS + (rr & 31);
        s.tagc[0][rr] = g_tagc[gr];
        s.tagc[1][rr] = g_tagc[G4 + gr];
        s.tagc[2][rr] = 0.f;
    }
    for (int i = tid; i < 2 * H_; i += 256) s.waffh[i >> 8][i & 255] = Waff[(i >> 8) * G4 + (i & 255)];
    for (int i = tid; i < NB * H_; i += 256) s.h[i >> 8][i & 255] = 0.f;
    for (int i = tid; i < NB * T_; i += 256)
        s.maskS[i >> 9][i & 511] = mask[(size_t)(bbase + (i >> 9)) * T_ + (i & 511)];
    if (tid < NB) s.pred[tid] = 2;
    __syncthreads();

    // per-thread cell state (threads 0..127 own (eb, ej))
    float c_reg = 0.f;
    const int eb = tid >> 5, ej = tid & 31;    // valid for tid < 128
    const int sb_ = wid;                        // score batch for wid < 4

    for (int t = 0; t < T_; ++t) {
        // ---- prefetch (consumed after the matvec) ----
        float gp[4];
        if (tid < 128) {
            const size_t gbase = ((size_t)(bbase + eb) * T_ + t) * G4 + (int)rank * JS + ej;
            #pragma unroll
            for (int g = 0; g < 4; ++g) gp[g] = __ldg(&g_gp[gbase + g * 256]);
        }
        float sp0 = 0.f, sp1 = 0.f;
        if (wid < 4 && lane == 0) {
            sp0 = __ldg(&g_sp[((size_t)(bbase + sb_) * T_ + t) * 2]);
            sp1 = __ldg(&g_sp[((size_t)(bbase + sb_) * T_ + t) * 2 + 1]);
        }

        // ---- phase 1: matvec partials via packed f32x2 ----
        float a2[NB];
        #pragma unroll
        for (int b = 0; b < NB; ++b) {
            const ulonglong2* x2 = (const ulonglong2*)&s.h[b][half * 128];
            unsigned long long acc0 = 0ULL, acc1 = 0ULL;
            #pragma unroll
            for (int i = 0; i < 32; ++i) {
                ulonglong2 w = wreg2[i];
                ulonglong2 xv = x2[i];
                fma2(acc0, w.x, xv.x);
                fma2(acc1, w.y, xv.y);
            }
            float2 f0 = unpack64(acc0), f1 = unpack64(acc1);
            a2[b] = (f0.x + f0.y) + (f1.x + f1.y);
        }
        *(float4*)&s.part[half][r][0] = make_float4(a2[0], a2[1], a2[2], a2[3]);
        __syncthreads();   // A

        // ---- phase 2: gates + cell update + DSMEM broadcast (tid < 128) ----
        const int par = t & 1;
        if (tid < 128) {
            const int pd = s.pred[eb];
            float gate[4];
            #pragma unroll
            for (int g = 0; g < 4; ++g) {
                const int rr = g * 32 + ej;
                gate[g] = gp[g] + s.tagc[pd][rr] + s.part[0][rr][eb] + s.part[1][rr][eb];
            }
            float cn = sigf(gate[1]) * c_reg + sigf(gate[0]) * tanhf(gate[2]);
            float hn = sigf(gate[3]) * tanhf(cn);
            float mi = s.maskS[eb][t];
            c_reg = mi * cn + (1.f - mi) * c_reg;
            uint32_t addr = (uint32_t)__cvta_generic_to_shared(
                &s.hnew[par][eb][(int)rank * JS + ej]);
            #pragma unroll
            for (int dst = 0; dst < CLUSTER; ++dst)
                st_cluster_f32(addr, (uint32_t)dst, hn);
        }
        cluster_sync_();   // B

        // ---- phase 3: h update + scores + pred + output ----
        #pragma unroll
        for (int i = 0; i < 4; ++i) {
            int idx = tid + i * 256;
            int ub = idx >> 8, uj = idx & 255;
            float mi = s.maskS[ub][t];
            s.h[ub][uj] = mi * s.hnew[par][ub][uj] + (1.f - mi) * s.h[ub][uj];
        }
        if (wid < 4) {
            float a0 = 0.f, a1 = 0.f;
            #pragma unroll
            for (int e = 0; e < 8; ++e) {
                float hv = s.hnew[par][sb_][lane + 32 * e];
                a0 = fmaf(s.waffh[0][lane + 32 * e], hv, a0);
                a1 = fmaf(s.waffh[1][lane + 32 * e], hv, a1);
            }
            #pragma unroll
            for (int o = 16; o > 0; o >>= 1) {
                a0 += __shfl_xor_sync(0xffffffffu, a0, o);
                a1 += __shfl_xor_sync(0xffffffffu, a1, o);
            }
            if (lane == 0) {
                float s0 = a0 + sp0, s1 = a1 + sp1;
                s.pred[sb_] = (s1 > s0) ? 1 : 0;
                if (rank == 0) {
                    float mx = fmaxf(s0, s1);
                    float lse = mx + logf(expf(s0 - mx) + expf(s1 - mx));
                    size_t o = ((size_t)(bbase + sb_) * T_ + t) * 2;
                    out[o]     = s0 - lse;
                    out[o + 1] = s1 - lse;
                }
            }
        }
        __syncthreads();   // C
    }
}

// ---------------- launch ----------------
extern "C" void kernel_launch(void* const* d_in, const int* in_sizes, int n_in,
                              void* d_out, int out_size) {
    const float* sents  = (const float*)d_in[0];
    const float* mask   = (const float*)d_in[1];
    const float* Wih    = (const float*)d_in[2];
    const float* Whh    = (const float*)d_in[3];
    const float* bih    = (const float*)d_in[4];
    const float* bhh    = (const float*)d_in[5];
    const float* Waff   = (const float*)d_in[6];
    const float* baff   = (const float*)d_in[7];
    const float* tag_em = (const float*)d_in[8];
    float* out = (float*)d_out;

    cudaFuncSetAttribute(gemm_kernel, cudaFuncAttributeMaxDynamicSharedMemorySize, GSM_TOTAL);
    cudaFuncSetAttribute(rnn_kernel, cudaFuncAttributeMaxDynamicSharedMemorySize,
                         (int)sizeof(RnnSmem));

    convA_kernel<<<(B_ * T_ * KIN) / (256 * 4), 256>>>(sents);
    convB_kernel<<<(G4 * KIN) / (256 * 4), 256>>>(Wih);
    prep_kernel<<<4, 256>>>(Wih, bih, bhh, tag_em);
    spre_kernel<<<(B_ * T_) / 8, 256>>>(sents, Waff, baff);
    gemm_kernel<<<dim3(G4 / 128, (B_ * T_) / 128), 256, GSM_TOTAL>>>();
    rnn_kernel<<<16 * CLUSTER, 256, sizeof(RnnSmem)>>>(mask, Whh, Waff, out);
}